// round 4
// baseline (speedup 1.0000x reference)
#include <cuda_runtime.h>

#define H 4096
#define E 8
#define H4 (H / 4)            // 1024 float4 per row
#define TPB 256
#define WARPS_PER_BLOCK 8
#define GRID (H / WARPS_PER_BLOCK)   // 512 blocks, one wave
#define K_ITERS (H4 / 32)     // 32 float4 per lane per row

__device__ int g_idx;
__device__ int g_flag;

__global__ void reset_kernel() { g_flag = 0; }

__global__ void __launch_bounds__(TPB, 4) fused_kernel(
    const float* __restrict__ x,
    const float* __restrict__ expert_w,
    const float* __restrict__ expert_b,
    const float* __restrict__ router_w,
    const float* __restrict__ router_b,
    const float* __restrict__ gate_w,
    const float* __restrict__ gate_b,
    float* __restrict__ out) {

    const int wid  = threadIdx.x >> 5;
    const int lane = threadIdx.x & 31;
    const int row  = blockIdx.x * WARPS_PER_BLOCK + wid;

    const float4* x4 = (const float4*)x;

    // ---- Block 0: router (one expert per warp), publish g_idx ----
    if (blockIdx.x == 0) {
        __shared__ float logits[E];
        const float4* w4 = (const float4*)(router_w + (size_t)wid * H);
        float s = 0.f;
        #pragma unroll 4
        for (int k = 0; k < K_ITERS; k++) {
            int i = lane + 32 * k;
            float4 a = x4[i];
            float4 b = w4[i];
            s += a.x * b.x + a.y * b.y + a.z * b.z + a.w * b.w;
        }
        #pragma unroll
        for (int o = 16; o > 0; o >>= 1) s += __shfl_xor_sync(0xFFFFFFFFu, s, o);
        if (lane == 0) logits[wid] = s + router_b[wid];
        __syncthreads();
        if (threadIdx.x == 0) {
            int best = 0;
            float bv = logits[0];
            #pragma unroll
            for (int e = 1; e < E; e++)
                if (logits[e] > bv) { bv = logits[e]; best = e; }  // first-max
            g_idx = best;
            __threadfence();
            *(volatile int*)&g_flag = 1;
        }
    }

    // ---- Phase 1 (all warps): gate dot — independent of router ----
    const float4* g4 = (const float4*)(gate_w + (size_t)row * H);
    float sg = 0.f;
    #pragma unroll 4
    for (int k = 0; k < K_ITERS; k++) {
        int i = lane + 32 * k;
        float4 a = x4[i];
        float4 b = g4[i];
        sg += a.x * b.x + a.y * b.y + a.z * b.z + a.w * b.w;
    }

    // ---- Wait for router result (gate phase >> router time, so ~free) ----
    int idx;
    if (lane == 0) {
        while (*(volatile int*)&g_flag == 0) { __nanosleep(40); }
        idx = *(volatile int*)&g_idx;
    }
    idx = __shfl_sync(0xFFFFFFFFu, idx, 0);

    // ---- Phase 2: expert dot ----
    const float4* e4 = (const float4*)(expert_w + ((size_t)idx * H + row) * H);
    float se = 0.f;
    #pragma unroll 4
    for (int k = 0; k < K_ITERS; k++) {
        int i = lane + 32 * k;
        float4 a = x4[i];
        float4 b = e4[i];
        se += a.x * b.x + a.y * b.y + a.z * b.z + a.w * b.w;
    }

    // ---- Warp reductions (shfl only, no syncthreads) ----
    #pragma unroll
    for (int o = 16; o > 0; o >>= 1) {
        sg += __shfl_xor_sync(0xFFFFFFFFu, sg, o);
        se += __shfl_xor_sync(0xFFFFFFFFu, se, o);
    }

    if (lane == 0) {
        float mix = tanhf(se + expert_b[(size_t)idx * H + row]);
        float z = sg + gate_b[row];
        float g = 1.f / (1.f + expf(-z));
        float xv = x[row];
        out[row] = g * mix + (1.f - g) * xv;
    }
}

extern "C" void kernel_launch(void* const* d_in, const int* in_sizes, int n_in,
                              void* d_out, int out_size) {
    const float* x        = (const float*)d_in[0];  // [1, H]
    const float* expert_w = (const float*)d_in[1];  // [E, H, H]
    const float* expert_b = (const float*)d_in[2];  // [E, H]
    const float* router_w = (const float*)d_in[3];  // [E, H]
    const float* router_b = (const float*)d_in[4];  // [E]
    const float* gate_w   = (const float*)d_in[5];  // [H, H]
    const float* gate_b   = (const float*)d_in[6];  // [H]
    float* out = (float*)d_out;                     // [1, H]

    reset_kernel<<<1, 1>>>();
    fused_kernel<<<GRID, TPB>>>(x, expert_w, expert_b, router_w, router_b,
                                gate_w, gate_b, out);
}

// round 5
// speedup vs baseline: 1.1391x; 1.1391x over previous
#include <cuda_runtime.h>

#define H 4096
#define E 8
#define H4 1024                    // float4 per row
#define TPB 256
#define ROWS_PER_BLOCK 4           // 8 warps, 2 warps per row
#define GRID (H / ROWS_PER_BLOCK)  // 1024 blocks
#define HALF4 (H4 / 2)             // 512 float4 per half-row
#define K_ITERS (HALF4 / 32)       // 16 float4 per lane per half

__device__ unsigned long long g_best;  // (sortable_logit << 32) | (7 - e); 0 == -inf sentinel
__device__ int g_rcnt;                 // router blocks completed (0..8)
__device__ int g_done;                 // blocks finished (self-reset)

__device__ __forceinline__ unsigned int f2sortable(float f) {
    unsigned int u = __float_as_uint(f);
    return (u & 0x80000000u) ? ~u : (u | 0x80000000u);
}

__global__ void __launch_bounds__(TPB, 7) fused_kernel(
    const float* __restrict__ x,
    const float* __restrict__ expert_w,
    const float* __restrict__ expert_b,
    const float* __restrict__ router_w,
    const float* __restrict__ router_b,
    const float* __restrict__ gate_w,
    const float* __restrict__ gate_b,
    float* __restrict__ out) {

    const int wid  = threadIdx.x >> 5;
    const int lane = threadIdx.x & 31;
    const float4* x4 = (const float4*)x;

    __shared__ float s_red[8];

    // ---- Blocks 0..7: router — one expert per block (16 KB dot, all 8 warps) ----
    if (blockIdx.x < E) {
        const int e = blockIdx.x;
        const float4* w4 = (const float4*)(router_w + (size_t)e * H);
        float s = 0.f;
        #pragma unroll
        for (int k = 0; k < H4 / TPB; k++) {
            int i = threadIdx.x + k * TPB;
            float4 a = x4[i];
            float4 b = w4[i];
            s += a.x * b.x + a.y * b.y + a.z * b.z + a.w * b.w;
        }
        #pragma unroll
        for (int o = 16; o > 0; o >>= 1) s += __shfl_xor_sync(0xFFFFFFFFu, s, o);
        if (lane == 0) s_red[wid] = s;
        __syncthreads();
        if (threadIdx.x == 0) {
            float v = router_b[e];
            #pragma unroll
            for (int w = 0; w < 8; w++) v += s_red[w];
            unsigned long long key =
                ((unsigned long long)f2sortable(v) << 32) | (unsigned long long)(7 - e);
            atomicMax(&g_best, key);
            __threadfence();
            atomicAdd(&g_rcnt, 1);
        }
        __syncthreads();   // s_red reused below
    }

    // ---- All blocks: 4 rows, 2 warps per row (split-K halves) ----
    const int row  = blockIdx.x * ROWS_PER_BLOCK + (wid >> 1);
    const int half = wid & 1;
    const int base = half * HALF4;

    // Phase 1: gate dot (independent of router)
    const float4* g4 = (const float4*)(gate_w + (size_t)row * H);
    float sg = 0.f;
    #pragma unroll 4
    for (int k = 0; k < K_ITERS; k++) {
        int i = base + lane + 32 * k;
        float4 a = x4[i];
        float4 b = g4[i];
        sg += a.x * b.x + a.y * b.y + a.z * b.z + a.w * b.w;
    }

    // Wait for router (gate phase >> router latency, so effectively free)
    int idx;
    if (lane == 0) {
        while (*(volatile int*)&g_rcnt < E) { __nanosleep(20); }
        __threadfence();
        unsigned long long b = *(volatile unsigned long long*)&g_best;
        idx = 7 - (int)(b & 7ULL);
    }
    idx = __shfl_sync(0xFFFFFFFFu, idx, 0);

    // Phase 2: expert dot
    const float4* e4 = (const float4*)(expert_w + ((size_t)idx * H + row) * H);
    float se = 0.f;
    #pragma unroll 4
    for (int k = 0; k < K_ITERS; k++) {
        int i = base + lane + 32 * k;
        float4 a = x4[i];
        float4 b = e4[i];
        se += a.x * b.x + a.y * b.y + a.z * b.z + a.w * b.w;
    }

    // Warp reductions
    #pragma unroll
    for (int o = 16; o > 0; o >>= 1) {
        sg += __shfl_xor_sync(0xFFFFFFFFu, sg, o);
        se += __shfl_xor_sync(0xFFFFFFFFu, se, o);
    }

    // Combine the two half-row partials via smem
    __shared__ float s_se[8], s_sg[8];
    if (lane == 0) { s_se[wid] = se; s_sg[wid] = sg; }
    __syncthreads();

    if ((wid & 1) == 0 && lane == 0) {
        float SE = s_se[wid] + s_se[wid + 1];
        float SG = s_sg[wid] + s_sg[wid + 1];
        float mix = tanhf(SE + expert_b[(size_t)idx * H + row]);
        float z = SG + gate_b[row];
        float g = 1.f / (1.f + expf(-z));
        float xv = x[row];
        out[row] = g * mix + (1.f - g) * xv;
    }

    // Self-cleaning reset: last block to finish restores globals for next replay
    __syncthreads();
    if (threadIdx.x == 0) {
        int d = atomicAdd(&g_done, 1);
        if (d == GRID - 1) {
            g_done = 0;
            g_rcnt = 0;
            g_best = 0ULL;
            __threadfence();
        }
    }
}

extern "C" void kernel_launch(void* const* d_in, const int* in_sizes, int n_in,
                              void* d_out, int out_size) {
    const float* x        = (const float*)d_in[0];  // [1, H]
    const float* expert_w = (const float*)d_in[1];  // [E, H, H]
    const float* expert_b = (const float*)d_in[2];  // [E, H]
    const float* router_w = (const float*)d_in[3];  // [E, H]
    const float* router_b = (const float*)d_in[4];  // [E]
    const float* gate_w   = (const float*)d_in[5];  // [H, H]
    const float* gate_b   = (const float*)d_in[6];  // [H]
    float* out = (float*)d_out;                     // [1, H]

    fused_kernel<<<GRID, TPB>>>(x, expert_w, expert_b, router_w, router_b,
                                gate_w, gate_b, out);
}